// round 2
// baseline (speedup 1.0000x reference)
#include <cuda_runtime.h>
#include <cuda_bf16.h>

#define N_NODES 50000
#define N_EDGES 1600000
#define F_IN    128
#define F_OUT   8
#define K_TAPS  4
#define MAX_POWER 25   // F_OUT*(K_TAPS-1)+1

// s-buffer: row 0 = v0 (feature row-sums of x), rows 1..25 = S^p v0.
// 26 * 50000 * 4B = 5.2 MB device-global scratch (no allocation allowed).
__device__ float g_s[(MAX_POWER + 1) * N_NODES];

// ---------------------------------------------------------------------------
// Kernel 1: v0[n] = sum_f x[n,f]  (warp per node, float4 lanes), and zero s[1].
// ---------------------------------------------------------------------------
__global__ void gfl_rowsum_kernel(const float* __restrict__ x) {
    int gid  = blockIdx.x * blockDim.x + threadIdx.x;
    int warp = gid >> 5;
    int lane = threadIdx.x & 31;
    if (warp < N_NODES) {
        const float4* xr = reinterpret_cast<const float4*>(x + (size_t)warp * F_IN);
        float4 v = __ldg(&xr[lane]);            // 32 lanes * 4 floats = 128
        float s = v.x + v.y + v.z + v.w;
        #pragma unroll
        for (int o = 16; o; o >>= 1) s += __shfl_xor_sync(0xffffffffu, s, o);
        if (lane == 0) g_s[warp] = s;
    }
    // zero s[1] so iteration p=1 can atomically accumulate into it
    if (gid < N_NODES) g_s[N_NODES + gid] = 0.0f;
}

// ---------------------------------------------------------------------------
// Kernel 2: one SpMV power step. Thread per edge:
//   s[p][rows[e]] += vals[e] * s[p-1][cols[e]]
// Also zeroes s[p+1] (safe: next iteration's atomics are after this kernel).
// ---------------------------------------------------------------------------
__global__ void gfl_spmv_kernel(const int*   __restrict__ rows,
                                const int*   __restrict__ cols,
                                const float* __restrict__ vals,
                                int p) {
    int e = blockIdx.x * blockDim.x + threadIdx.x;
    const float* __restrict__ vin  = g_s + (size_t)(p - 1) * N_NODES;
    float*       __restrict__ vout = g_s + (size_t)p * N_NODES;
    if (e < N_EDGES) {
        int   c = __ldg(&cols[e]);
        int   r = __ldg(&rows[e]);
        float w = __ldg(&vals[e]);
        atomicAdd(&vout[r], w * __ldg(&vin[c]));
    }
    if (p < MAX_POWER && e < N_NODES) {
        g_s[(size_t)(p + 1) * N_NODES + e] = 0.0f;
    }
}

// ---------------------------------------------------------------------------
// Kernel 3: y[n,o] = sum_k coeff[o,k] * s[o*(K-1)+k + 1][n]
// Thread per node; s reads are coalesced (stride across n).
// ---------------------------------------------------------------------------
__global__ void gfl_out_kernel(const float* __restrict__ coeff,
                               float* __restrict__ y) {
    int n = blockIdx.x * blockDim.x + threadIdx.x;
    if (n >= N_NODES) return;

    float sv[MAX_POWER];
    #pragma unroll
    for (int p = 0; p < MAX_POWER; p++)
        sv[p] = g_s[(size_t)(p + 1) * N_NODES + n];

    #pragma unroll
    for (int o = 0; o < F_OUT; o++) {
        float acc = 0.0f;
        #pragma unroll
        for (int k = 0; k < K_TAPS; k++)
            acc += __ldg(&coeff[o * K_TAPS + k]) * sv[o * (K_TAPS - 1) + k];
        y[(size_t)n * F_OUT + o] = acc;
    }
}

// ---------------------------------------------------------------------------
extern "C" void kernel_launch(void* const* d_in, const int* in_sizes, int n_in,
                              void* d_out, int out_size) {
    const float* x     = (const float*)d_in[0];
    const int*   rows  = (const int*)  d_in[1];
    const int*   cols  = (const int*)  d_in[2];
    const float* vals  = (const float*)d_in[3];
    const float* coeff = (const float*)d_in[4];
    float*       y     = (float*)d_out;

    const int T = 256;

    // v0 = row-sums (warp per node) + zero s[1]
    {
        int warps_needed = N_NODES;
        int blocks = (warps_needed * 32 + T - 1) / T;
        gfl_rowsum_kernel<<<blocks, T>>>(x);
    }

    // 25 SpMV power steps
    {
        int blocks = (N_EDGES + T - 1) / T;
        for (int p = 1; p <= MAX_POWER; p++) {
            gfl_spmv_kernel<<<blocks, T>>>(rows, cols, vals, p);
        }
    }

    // tap mixing
    {
        int blocks = (N_NODES + T - 1) / T;
        gfl_out_kernel<<<blocks, T>>>(coeff, y);
    }
}

// round 3
// speedup vs baseline: 1.1027x; 1.1027x over previous
#include <cuda_runtime.h>
#include <cuda_bf16.h>

#define N_NODES  50000
#define N_EDGES  1600000
#define F_IN     128
#define F_OUT    8
#define K_TAPS   4
#define MAX_POWER 25   // F_OUT*(K_TAPS-1)+1
#define SCAN_T   1024

// ---- device-global scratch (no allocation allowed) ----
// s-buffer: row 0 = v0 (feature row-sums of x), rows 1..25 = S^p v0.
__device__ float g_s[(MAX_POWER + 1) * N_NODES];          // 5.2 MB
__device__ int   g_cnt[N_NODES];                          // per-row degree
__device__ int   g_rowptr[N_NODES + 1];                   // CSR row pointers
__device__ int   g_fill[N_NODES];                         // scatter cursors
__device__ int2  g_csr[N_EDGES];                          // packed {col, val-bits}, 12.8 MB

// ---------------------------------------------------------------------------
// Kernel 1: v0[n] = sum_f x[n,f]  (warp per node, float4 lanes) + zero g_cnt.
// ---------------------------------------------------------------------------
__global__ void gfl_init_kernel(const float* __restrict__ x) {
    int gid  = blockIdx.x * blockDim.x + threadIdx.x;
    int warp = gid >> 5;
    int lane = threadIdx.x & 31;
    if (warp < N_NODES) {
        const float4* xr = reinterpret_cast<const float4*>(x + (size_t)warp * F_IN);
        float4 v = __ldg(&xr[lane]);            // 32 lanes * 4 floats = 128
        float s = v.x + v.y + v.z + v.w;
        #pragma unroll
        for (int o = 16; o; o >>= 1) s += __shfl_xor_sync(0xffffffffu, s, o);
        if (lane == 0) g_s[warp] = s;
    }
    if (gid < N_NODES) g_cnt[gid] = 0;
}

// ---------------------------------------------------------------------------
// Kernel 2: histogram of destination rows.
// ---------------------------------------------------------------------------
__global__ void gfl_hist_kernel(const int* __restrict__ rows) {
    int e = blockIdx.x * blockDim.x + threadIdx.x;
    if (e < N_EDGES) atomicAdd(&g_cnt[__ldg(&rows[e])], 1);
}

// ---------------------------------------------------------------------------
// Kernel 3: single-block exclusive scan of g_cnt -> g_rowptr (+ fill cursors).
// ---------------------------------------------------------------------------
__global__ void gfl_scan_kernel() {
    __shared__ int part[SCAN_T];
    int t = threadIdx.x;
    const int CH = (N_NODES + SCAN_T - 1) / SCAN_T;       // 49
    int beg = t * CH;
    int end = beg + CH; if (end > N_NODES) end = N_NODES;

    int s = 0;
    for (int i = beg; i < end; i++) s += g_cnt[i];
    part[t] = s;
    __syncthreads();

    // Hillis-Steele inclusive scan over the 1024 partials
    #pragma unroll
    for (int off = 1; off < SCAN_T; off <<= 1) {
        int v = (t >= off) ? part[t - off] : 0;
        __syncthreads();
        part[t] += v;
        __syncthreads();
    }
    int run = (t == 0) ? 0 : part[t - 1];                 // exclusive prefix

    for (int i = beg; i < end; i++) {
        int c = g_cnt[i];
        g_rowptr[i] = run;
        g_fill[i]   = run;
        run += c;
    }
    if (t == SCAN_T - 1) g_rowptr[N_NODES] = run;         // = N_EDGES
}

// ---------------------------------------------------------------------------
// Kernel 4: scatter edges into CSR slots (order within a row is arbitrary).
// ---------------------------------------------------------------------------
__global__ void gfl_scatter_kernel(const int*   __restrict__ rows,
                                   const int*   __restrict__ cols,
                                   const float* __restrict__ vals) {
    int e = blockIdx.x * blockDim.x + threadIdx.x;
    if (e >= N_EDGES) return;
    int r = __ldg(&rows[e]);
    int pos = atomicAdd(&g_fill[r], 1);
    int2 pk;
    pk.x = __ldg(&cols[e]);
    pk.y = __float_as_int(__ldg(&vals[e]));
    g_csr[pos] = pk;
}

// ---------------------------------------------------------------------------
// Kernel 5: CSR SpMV power step, warp per row, no atomics, no zeroing.
//   s[p][r] = sum_{i in row r} val_i * s[p-1][col_i]
// ---------------------------------------------------------------------------
__global__ void gfl_spmv_csr_kernel(int p) {
    int gid  = blockIdx.x * blockDim.x + threadIdx.x;
    int row  = gid >> 5;
    int lane = gid & 31;
    if (row >= N_NODES) return;

    const float* __restrict__ vin = g_s + (size_t)(p - 1) * N_NODES;
    int beg = __ldg(&g_rowptr[row]);
    int end = __ldg(&g_rowptr[row + 1]);

    float acc = 0.0f;
    for (int i = beg + lane; i < end; i += 32) {
        int2 e = __ldg(&g_csr[i]);
        acc += __int_as_float(e.y) * __ldg(&vin[e.x]);
    }
    #pragma unroll
    for (int o = 16; o; o >>= 1) acc += __shfl_xor_sync(0xffffffffu, acc, o);
    if (lane == 0) g_s[(size_t)p * N_NODES + row] = acc;
}

// ---------------------------------------------------------------------------
// Kernel 6: y[n,o] = sum_k coeff[o,k] * s[o*(K-1)+k + 1][n]
// ---------------------------------------------------------------------------
__global__ void gfl_out_kernel(const float* __restrict__ coeff,
                               float* __restrict__ y) {
    int n = blockIdx.x * blockDim.x + threadIdx.x;
    if (n >= N_NODES) return;

    float sv[MAX_POWER];
    #pragma unroll
    for (int p = 0; p < MAX_POWER; p++)
        sv[p] = g_s[(size_t)(p + 1) * N_NODES + n];

    #pragma unroll
    for (int o = 0; o < F_OUT; o++) {
        float acc = 0.0f;
        #pragma unroll
        for (int k = 0; k < K_TAPS; k++)
            acc += __ldg(&coeff[o * K_TAPS + k]) * sv[o * (K_TAPS - 1) + k];
        y[(size_t)n * F_OUT + o] = acc;
    }
}

// ---------------------------------------------------------------------------
extern "C" void kernel_launch(void* const* d_in, const int* in_sizes, int n_in,
                              void* d_out, int out_size) {
    const float* x     = (const float*)d_in[0];
    const int*   rows  = (const int*)  d_in[1];
    const int*   cols  = (const int*)  d_in[2];
    const float* vals  = (const float*)d_in[3];
    const float* coeff = (const float*)d_in[4];
    float*       y     = (float*)d_out;

    const int T = 256;
    const int edge_blocks = (N_EDGES + T - 1) / T;

    // v0 row-sums + zero degree counters
    gfl_init_kernel<<<(N_NODES * 32 + T - 1) / T, T>>>(x);

    // build CSR (amortized over the 25 SpMVs)
    gfl_hist_kernel<<<edge_blocks, T>>>(rows);
    gfl_scan_kernel<<<1, SCAN_T>>>();
    gfl_scatter_kernel<<<edge_blocks, T>>>(rows, cols, vals);

    // 25 SpMV power steps (warp per row)
    const int spmv_blocks = (N_NODES * 32 + T - 1) / T;
    for (int p = 1; p <= MAX_POWER; p++) {
        gfl_spmv_csr_kernel<<<spmv_blocks, T>>>(p);
    }

    // tap mixing
    gfl_out_kernel<<<(N_NODES + T - 1) / T, T>>>(coeff, y);
}